// round 4
// baseline (speedup 1.0000x reference)
#include <cuda_runtime.h>
#include <cstdint>

// Problem: AveragePrecision_4690104287320
// output: (16,3,128,128,85) f32 -> 786,432 rows of 85 floats
// anchors: unused. targets: (16,50,5) f32 -> identity copy.
// Out: pred_out (786432 x 7 f32) then target copy (4000 f32).

#define CONF_THRESHOLD 0.25f

constexpr int ROWS    = 128;                 // rows (threads) per tile
constexpr int VROW    = 85;
constexpr int SMEM_F  = ROWS * VROW;         // 10880 floats per tile
constexpr int TILE_B  = SMEM_F * 4;          // 43520 bytes
constexpr int OUT_F   = ROWS * 7;            // 896 floats
constexpr int OUT_B   = OUT_F * 4;           // 3584 bytes
constexpr int GRID    = 296;                 // 2 persistent blocks / SM (148-SM safe)
constexpr int DSMEM_B = 2 * TILE_B;          // two buffers

__device__ __forceinline__ uint32_t smem_u32(const void* p) {
    uint32_t a;
    asm("{ .reg .u64 t; cvta.to.shared.u64 t, %1; cvt.u32.u64 %0, t; }" : "=r"(a) : "l"(p));
    return a;
}

__device__ __forceinline__ void mbar_wait(uint32_t mb, int phase) {
    uint32_t done;
    asm volatile(
        "{\n\t.reg .pred p;\n\t"
        "mbarrier.try_wait.parity.acquire.cta.shared::cta.b64 p, [%1], %2;\n\t"
        "selp.b32 %0, 1, 0, p;\n\t}"
        : "=r"(done) : "r"(mb), "r"(phase) : "memory");
    if (!done) {
        asm volatile(
            "{\n\t.reg .pred P1;\n\t"
            "WAIT_LOOP_%=:\n\t"
            "mbarrier.try_wait.parity.acquire.cta.shared::cta.b64 P1, [%0], %1, 0x989680;\n\t"
            "@P1 bra.uni WAIT_DONE_%=;\n\t"
            "bra.uni WAIT_LOOP_%=;\n\t"
            "WAIT_DONE_%=:\n\t}"
            :: "r"(mb), "r"(phase) : "memory");
    }
}

__global__ void __launch_bounds__(ROWS)
yolo_fuse_kernel(const float* __restrict__ pred,
                 float* __restrict__ out,
                 const float4* __restrict__ targ4,
                 float4* __restrict__ targ_out4,
                 int ntiles)
{
    extern __shared__ __align__(16) float smem[];      // 2 tiles
    __shared__ __align__(8) uint64_t mbar[2];

    const int tid = threadIdx.x;
    const uint32_t mb0 = smem_u32(&mbar[0]);
    const uint32_t mb1 = smem_u32(&mbar[1]);

    if (tid == 0) {
        asm volatile("mbarrier.init.shared.b64 [%0], %1;" :: "r"(mb0), "r"(1) : "memory");
        asm volatile("mbarrier.init.shared.b64 [%0], %1;" :: "r"(mb1), "r"(1) : "memory");
    }
    __syncthreads();

    // fused targets copy (16KB total, blocks 0..7)
    if (blockIdx.x < 8 && tid < 125) {
        int idx = (int)blockIdx.x * 125 + tid;
        targ_out4[idx] = targ4[idx];
    }

    // prefetch first tile into buffer 0
    const int t0 = blockIdx.x;
    if (t0 < ntiles && tid == 0) {
        asm volatile("mbarrier.arrive.expect_tx.shared.b64 _, [%0], %1;"
                     :: "r"(mb0), "r"((uint32_t)TILE_B) : "memory");
        asm volatile("cp.async.bulk.shared::cta.global.mbarrier::complete_tx::bytes "
                     "[%0], [%1], %2, [%3];"
                     :: "r"(smem_u32(smem)), "l"(pred + (long long)t0 * SMEM_F),
                        "r"((uint32_t)TILE_B), "r"(mb0) : "memory");
    }

    int ph0 = 0, ph1 = 0;
    int i = 0;
    for (int t = t0; t < ntiles; t += GRID, i++) {
        const int b = i & 1;
        float* buf = smem + b * SMEM_F;
        const uint32_t mb = b ? mb1 : mb0;

        // prefetch next tile into the other buffer
        const int nt = t + GRID;
        if (nt < ntiles && tid == 0) {
            const int nb = b ^ 1;
            const uint32_t nmb = nb ? mb1 : mb0;
            // ensure the bulk store that last read buffer nb has finished reading
            asm volatile("cp.async.bulk.wait_group.read 0;" ::: "memory");
            asm volatile("mbarrier.arrive.expect_tx.shared.b64 _, [%0], %1;"
                         :: "r"(nmb), "r"((uint32_t)TILE_B) : "memory");
            asm volatile("cp.async.bulk.shared::cta.global.mbarrier::complete_tx::bytes "
                         "[%0], [%1], %2, [%3];"
                         :: "r"(smem_u32(smem + nb * SMEM_F)),
                            "l"(pred + (long long)nt * SMEM_F),
                            "r"((uint32_t)TILE_B), "r"(nmb) : "memory");
        }

        // wait for current tile
        if (b) { mbar_wait(mb1, ph1); ph1 ^= 1; }
        else   { mbar_wait(mb0, ph0); ph0 ^= 1; }

        // ---- thread-per-row scan (stride-85: bank-conflict-free) ----
        const float* row = buf + tid * VROW;
        const float b0 = row[0], b1v = row[1], b2 = row[2], b3 = row[3];
        const float obj = row[4];

        float m0 = row[5], m1 = row[6], m2 = row[7], m3 = row[8];
        int   i0 = 0,      i1 = 1,      i2 = 2,      i3 = 3;
        #pragma unroll
        for (int k = 1; k < 20; k++) {
            const float v0 = row[5 + 4 * k];
            const float v1 = row[6 + 4 * k];
            const float v2 = row[7 + 4 * k];
            const float v3 = row[8 + 4 * k];
            if (v0 > m0) { m0 = v0; i0 = 4 * k;     }
            if (v1 > m1) { m1 = v1; i1 = 4 * k + 1; }
            if (v2 > m2) { m2 = v2; i2 = 4 * k + 2; }
            if (v3 > m3) { m3 = v3; i3 = 4 * k + 3; }
        }
        float best = m0; int bidx = i0;
        if (m1 > best || (m1 == best && i1 < bidx)) { best = m1; bidx = i1; }
        if (m2 > best || (m2 == best && i2 < bidx)) { best = m2; bidx = i2; }
        if (m3 > best || (m3 == best && i3 < bidx)) { best = m3; bidx = i3; }

        const float conf = best * obj;
        const bool  keep = conf > CONF_THRESHOLD;

        float r[7];
        r[0] = keep ? b0  : 0.0f;
        r[1] = keep ? b1v : 0.0f;
        r[2] = keep ? b2  : 0.0f;
        r[3] = keep ? b3  : 0.0f;
        r[4] = keep ? obj : 0.0f;
        r[5] = keep ? (float)bidx : 0.0f;
        r[6] = keep ? conf : 0.0f;

        __syncthreads();                     // all reads of this tile done
        #pragma unroll
        for (int j = 0; j < 7; j++) buf[tid * 7 + j] = r[j];  // stride-7: conflict-free
        __syncthreads();

        // ---- bulk store 3584 B shared -> global ----
        if (tid == 0) {
            asm volatile("fence.proxy.async.shared::cta;" ::: "memory");
            asm volatile("cp.async.bulk.global.shared::cta.bulk_group [%0], [%1], %2;"
                         :: "l"(out + (long long)t * OUT_F), "r"(smem_u32(buf)),
                            "r"((uint32_t)OUT_B) : "memory");
            asm volatile("cp.async.bulk.commit_group;" ::: "memory");
        }
    }

    // drain outstanding bulk stores before exit
    if (tid == 0) {
        asm volatile("cp.async.bulk.wait_group 0;" ::: "memory");
    }
}

extern "C" void kernel_launch(void* const* d_in, const int* in_sizes, int n_in,
                              void* d_out, int out_size)
{
    const float* output  = (const float*)d_in[0];   // (16,3,128,128,85)
    const float* targets = (const float*)d_in[2];   // (16,50,5)

    float* out = (float*)d_out;

    const int nrows  = in_sizes[0] / VROW;          // 786432 (multiple of 128)
    const int ntiles = nrows / ROWS;                // 6144
    float* targ_out = out + (long long)nrows * 7;

    static bool attr_set = false;
    if (!attr_set) {
        cudaFuncSetAttribute(yolo_fuse_kernel,
                             cudaFuncAttributeMaxDynamicSharedMemorySize, DSMEM_B);
        attr_set = true;
    }

    yolo_fuse_kernel<<<GRID, ROWS, DSMEM_B>>>(output, out,
                                              (const float4*)targets,
                                              (float4*)targ_out, ntiles);
}